// round 1
// baseline (speedup 1.0000x reference)
#include <cuda_runtime.h>
#include <cuda_bf16.h>

#define NNODES 50000
#define NEDGES 600000
#define C_IN   128
#define C_HID  128
#define C_OUT  40

// ---------------- scratch (static device globals; no allocation) -------------
__device__ float g_h1  [NNODES * C_HID];   // x@W1, later relu'd layer-1 output (in-place)
__device__ float g_agg1[NNODES * C_HID];
__device__ float g_h2  [NNODES * C_OUT];   // h@W2
__device__ float g_agg2[NNODES * C_OUT];
__device__ float g_deg [NNODES];
__device__ float g_dinv[NNODES];

// ---------------- utility: fill float buffer (float4 granularity) -----------
__global__ void fill4_kernel(float4* p, float v, int n4) {
    int i = blockIdx.x * blockDim.x + threadIdx.x;
    if (i < n4) p[i] = make_float4(v, v, v, v);
}

// ---------------- degree + dinv ----------------------------------------------
__global__ void degree_kernel(const int* __restrict__ ei) {
    int e = blockIdx.x * blockDim.x + threadIdx.x;
    if (e < NEDGES) {
        int d = ei[NEDGES + e];
        atomicAdd(&g_deg[d], 1.0f);
    }
}

__global__ void dinv_kernel() {
    int i = blockIdx.x * blockDim.x + threadIdx.x;
    if (i < NNODES) g_dinv[i] = rsqrtf(g_deg[i]);
}

// ---------------- GEMM: [M,128] @ [128,128] -> [M,128] -----------------------
// Tile 128x128, K-step 16, 256 threads, 8x8 micro-tile per thread.
__global__ __launch_bounds__(256) void gemm128_kernel(
    const float* __restrict__ A, const float* __restrict__ W,
    float* __restrict__ C, int M)
{
    __shared__ float xs[16][132];   // k-major transposed x tile (+pad)
    __shared__ float ws[16][128];

    int tid = threadIdx.x;
    int tx = tid & 15;          // 0..15 -> 8 cols each
    int ty = tid >> 4;          // 0..15 -> 8 rows each
    int r0 = blockIdx.x * 128;

    float acc[8][8];
#pragma unroll
    for (int i = 0; i < 8; i++)
#pragma unroll
        for (int j = 0; j < 8; j++) acc[i][j] = 0.f;

    for (int k0 = 0; k0 < 128; k0 += 16) {
        // x tile: 128 rows x 16 k = 512 float4 loads
#pragma unroll
        for (int L = tid; L < 512; L += 256) {
            int r  = L >> 2;
            int kg = L & 3;
            float4 v = make_float4(0.f, 0.f, 0.f, 0.f);
            int row = r0 + r;
            if (row < M)
                v = *(const float4*)&A[(size_t)row * 128 + k0 + kg * 4];
            xs[kg * 4 + 0][r] = v.x;
            xs[kg * 4 + 1][r] = v.y;
            xs[kg * 4 + 2][r] = v.z;
            xs[kg * 4 + 3][r] = v.w;
        }
        // W tile: 16 x 128 = 512 float4 loads
#pragma unroll
        for (int L = tid; L < 512; L += 256) {
            int k  = L >> 5;
            int cg = L & 31;
            *(float4*)&ws[k][cg * 4] =
                *(const float4*)&W[(size_t)(k0 + k) * 128 + cg * 4];
        }
        __syncthreads();

#pragma unroll
        for (int k = 0; k < 16; ++k) {
            float a[8], b[8];
            *(float4*)(a)     = *(const float4*)&xs[k][ty * 8];
            *(float4*)(a + 4) = *(const float4*)&xs[k][ty * 8 + 4];
            *(float4*)(b)     = *(const float4*)&ws[k][tx * 8];
            *(float4*)(b + 4) = *(const float4*)&ws[k][tx * 8 + 4];
#pragma unroll
            for (int i = 0; i < 8; i++)
#pragma unroll
                for (int j = 0; j < 8; j++)
                    acc[i][j] = fmaf(a[i], b[j], acc[i][j]);
        }
        __syncthreads();
    }

#pragma unroll
    for (int i = 0; i < 8; i++) {
        int row = r0 + ty * 8 + i;
        if (row < M) {
            *(float4*)&C[(size_t)row * 128 + tx * 8] =
                make_float4(acc[i][0], acc[i][1], acc[i][2], acc[i][3]);
            *(float4*)&C[(size_t)row * 128 + tx * 8 + 4] =
                make_float4(acc[i][4], acc[i][5], acc[i][6], acc[i][7]);
        }
    }
}

// ---------------- GEMM: [M,128] @ [128,40] -> [M,40] -------------------------
// Tile 128 rows x 40 cols, K-step 16, 160 threads, 8x4 micro-tile.
__global__ __launch_bounds__(160) void gemm40_kernel(
    const float* __restrict__ A, const float* __restrict__ W,
    float* __restrict__ C, int M)
{
    __shared__ float xs[16][132];
    __shared__ float ws[16][40];

    int tid = threadIdx.x;        // 0..159
    int tx = tid % 10;            // 0..9  -> 4 cols each
    int ty = tid / 10;            // 0..15 -> 8 rows each
    int r0 = blockIdx.x * 128;

    float acc[8][4];
#pragma unroll
    for (int i = 0; i < 8; i++)
#pragma unroll
        for (int j = 0; j < 4; j++) acc[i][j] = 0.f;

    for (int k0 = 0; k0 < 128; k0 += 16) {
        for (int L = tid; L < 512; L += 160) {
            int r  = L >> 2;
            int kg = L & 3;
            float4 v = make_float4(0.f, 0.f, 0.f, 0.f);
            int row = r0 + r;
            if (row < M)
                v = *(const float4*)&A[(size_t)row * 128 + k0 + kg * 4];
            xs[kg * 4 + 0][r] = v.x;
            xs[kg * 4 + 1][r] = v.y;
            xs[kg * 4 + 2][r] = v.z;
            xs[kg * 4 + 3][r] = v.w;
        }
        // W tile: 16 x 40 = 160 float4 loads
        {
            int L = tid;                          // exactly 160
            int k  = L / 10;
            int cg = L % 10;
            *(float4*)&ws[k][cg * 4] =
                *(const float4*)&W[(size_t)(k0 + k) * 40 + cg * 4];
        }
        __syncthreads();

#pragma unroll
        for (int k = 0; k < 16; ++k) {
            float a[8], b[4];
            *(float4*)(a)     = *(const float4*)&xs[k][ty * 8];
            *(float4*)(a + 4) = *(const float4*)&xs[k][ty * 8 + 4];
            *(float4*)(b)     = *(const float4*)&ws[k][tx * 4];
#pragma unroll
            for (int i = 0; i < 8; i++)
#pragma unroll
                for (int j = 0; j < 4; j++)
                    acc[i][j] = fmaf(a[i], b[j], acc[i][j]);
        }
        __syncthreads();
    }

#pragma unroll
    for (int i = 0; i < 8; i++) {
        int row = r0 + ty * 8 + i;
        if (row < M) {
            *(float4*)&C[(size_t)row * 40 + tx * 4] =
                make_float4(acc[i][0], acc[i][1], acc[i][2], acc[i][3]);
        }
    }
}

// ---------------- scatter for C=128: one warp per edge -----------------------
__global__ __launch_bounds__(256) void scatter128_kernel(const int* __restrict__ ei) {
    int w = (blockIdx.x * blockDim.x + threadIdx.x) >> 5;
    if (w >= NEDGES) return;
    int lane = threadIdx.x & 31;

    int s = 0, d = 0;
    float nrm = 0.f;
    if (lane == 0) {
        s = ei[w];
        d = ei[NEDGES + w];
        nrm = g_dinv[s] * g_dinv[d];
    }
    s   = __shfl_sync(0xffffffffu, s, 0);
    d   = __shfl_sync(0xffffffffu, d, 0);
    nrm = __shfl_sync(0xffffffffu, nrm, 0);

    float4 v = *(const float4*)&g_h1[(size_t)s * 128 + lane * 4];
    v.x *= nrm; v.y *= nrm; v.z *= nrm; v.w *= nrm;
    float* p = &g_agg1[(size_t)d * 128 + lane * 4];
    asm volatile("red.global.add.v4.f32 [%0], {%1, %2, %3, %4};"
                 :: "l"(p), "f"(v.x), "f"(v.y), "f"(v.z), "f"(v.w)
                 : "memory");
}

// ---------------- scatter for C=40: 10 float4 units per edge -----------------
__global__ __launch_bounds__(256) void scatter40_kernel(const int* __restrict__ ei) {
    int u = blockIdx.x * blockDim.x + threadIdx.x;
    if (u >= NEDGES * 10) return;
    int e = u / 10;
    int p = u % 10;
    int s = ei[e];
    int d = ei[NEDGES + e];
    float nrm = g_dinv[s] * g_dinv[d];

    float4 v = *(const float4*)&g_h2[(size_t)s * 40 + p * 4];
    v.x *= nrm; v.y *= nrm; v.z *= nrm; v.w *= nrm;
    float* q = &g_agg2[(size_t)d * 40 + p * 4];
    asm volatile("red.global.add.v4.f32 [%0], {%1, %2, %3, %4};"
                 :: "l"(q), "f"(v.x), "f"(v.y), "f"(v.z), "f"(v.w)
                 : "memory");
}

// ---------------- combine layer 1: agg + h*dinv^2 + b, relu, in-place h1 -----
__global__ __launch_bounds__(256) void combine1_kernel(const float* __restrict__ b1) {
    int idx = blockIdx.x * blockDim.x + threadIdx.x;   // float4 index
    if (idx >= NNODES * 32) return;
    int row = idx >> 5;
    int c4  = idx & 31;
    float di = g_dinv[row];
    float d2 = di * di;
    float4 a  = *(const float4*)&g_agg1[(size_t)idx * 4];
    float4 hv = *(const float4*)&g_h1 [(size_t)idx * 4];
    float4 bb = *(const float4*)&b1[c4 * 4];
    float4 r;
    r.x = fmaxf(fmaf(hv.x, d2, a.x) + bb.x, 0.f);
    r.y = fmaxf(fmaf(hv.y, d2, a.y) + bb.y, 0.f);
    r.z = fmaxf(fmaf(hv.z, d2, a.z) + bb.z, 0.f);
    r.w = fmaxf(fmaf(hv.w, d2, a.w) + bb.w, 0.f);
    *(float4*)&g_h1[(size_t)idx * 4] = r;
}

// ---------------- combine layer 2: agg + h*dinv^2 + b -> out -----------------
__global__ __launch_bounds__(256) void combine2_kernel(const float* __restrict__ b2,
                                                       float* __restrict__ out) {
    int idx = blockIdx.x * blockDim.x + threadIdx.x;   // float4 index
    if (idx >= NNODES * 10) return;
    int row = idx / 10;
    int c4  = idx % 10;
    float di = g_dinv[row];
    float d2 = di * di;
    float4 a  = *(const float4*)&g_agg2[(size_t)idx * 4];
    float4 hv = *(const float4*)&g_h2 [(size_t)idx * 4];
    float4 bb = *(const float4*)&b2[c4 * 4];
    float4 r;
    r.x = fmaf(hv.x, d2, a.x) + bb.x;
    r.y = fmaf(hv.y, d2, a.y) + bb.y;
    r.z = fmaf(hv.z, d2, a.z) + bb.z;
    r.w = fmaf(hv.w, d2, a.w) + bb.w;
    *(float4*)&out[(size_t)idx * 4] = r;
}

// -----------------------------------------------------------------------------
extern "C" void kernel_launch(void* const* d_in, const int* in_sizes, int n_in,
                              void* d_out, int out_size) {
    const float* x   = (const float*)d_in[0];
    const int*   ei  = (const int*)  d_in[1];
    const float* W1  = (const float*)d_in[2];
    const float* b1  = (const float*)d_in[3];
    const float* W2  = (const float*)d_in[4];
    const float* b2  = (const float*)d_in[5];
    float* out = (float*)d_out;

    float* agg1_p; cudaGetSymbolAddress((void**)&agg1_p, g_agg1);
    float* agg2_p; cudaGetSymbolAddress((void**)&agg2_p, g_agg2);
    float* deg_p;  cudaGetSymbolAddress((void**)&deg_p,  g_deg);
    float* h1_p;   cudaGetSymbolAddress((void**)&h1_p,   g_h1);
    float* h2_p;   cudaGetSymbolAddress((void**)&h2_p,   g_h2);

    // zero accumulators, deg = 1 (self loop)
    fill4_kernel<<<(NNODES * 32 + 255) / 256, 256>>>((float4*)agg1_p, 0.f, NNODES * 32);
    fill4_kernel<<<(NNODES * 10 + 255) / 256, 256>>>((float4*)agg2_p, 0.f, NNODES * 10);
    fill4_kernel<<<(NNODES / 4 + 255) / 256, 256>>>((float4*)deg_p, 1.f, NNODES / 4);

    degree_kernel<<<(NEDGES + 255) / 256, 256>>>(ei);
    dinv_kernel<<<(NNODES + 255) / 256, 256>>>();

    // layer 1
    gemm128_kernel<<<(NNODES + 127) / 128, 256>>>(x, W1, h1_p, NNODES);
    scatter128_kernel<<<(NEDGES * 32 + 255) / 256, 256>>>(ei);
    combine1_kernel<<<(NNODES * 32 + 255) / 256, 256>>>(b1);

    // layer 2
    gemm40_kernel<<<(NNODES + 127) / 128, 160>>>(h1_p, W2, h2_p, NNODES);
    scatter40_kernel<<<(NEDGES * 10 + 255) / 256, 256>>>(ei);
    combine2_kernel<<<(NNODES * 10 + 255) / 256, 256>>>(b2, out);
}